// round 5
// baseline (speedup 1.0000x reference)
#include <cuda_runtime.h>
#include <math.h>

// Problem constants
#define NNODES 50000
#define EMAX   1700000
#define FIN 8
#define FOUT 12
#define NP 6
#define F48 (FIN * NP)      // 48 floats per node
#define NQ  (F48 / 4)       // 12 float4 per node

// ---------------- device scratch (no allocations allowed) ----------------
__device__ float g_deg[NNODES];
__device__ float g_dinv[NNODES];
__device__ int   g_cnt[NNODES];
__device__ int   g_offs[NNODES + 1];
__device__ int   g_cursor[NNODES];
__device__ int2  g_csr[EMAX];          // {src, weight bits}

struct Params {
    float Mz[FIN][FOUT];   // Wz @ lzW[:, :FOUT]^T
    float Mh[FIN][FOUT];   // Wh @ lhW[:, :FOUT]^T
    float bz2[FOUT];
    float bh2[FOUT];
    float probs[NP];
};
__device__ Params g_p;

// ---------------- kernels ----------------

// Fold dense layers into 8x12 matrices; softmax(att). One tiny block.
__global__ void k_prep(const float* __restrict__ att,
                       const float* __restrict__ Wz, const float* __restrict__ bz,
                       const float* __restrict__ Wh, const float* __restrict__ bh,
                       const float* __restrict__ lzW, const float* __restrict__ lzb,
                       const float* __restrict__ lhW, const float* __restrict__ lhb) {
    int t = threadIdx.x;
    if (t < FIN * FOUT) {
        int f = t / FOUT, j = t % FOUT;
        float mz = 0.f, mh = 0.f;
        #pragma unroll
        for (int k = 0; k < FOUT; k++) {
            mz += Wz[f * FOUT + k] * lzW[j * (2 * FOUT) + k];
            mh += Wh[f * FOUT + k] * lhW[j * (2 * FOUT) + k];
        }
        g_p.Mz[f][j] = mz;
        g_p.Mh[f][j] = mh;
    } else if (t < FIN * FOUT + FOUT) {
        int j = t - FIN * FOUT;
        float b1 = lzb[j], b2 = lhb[j];
        #pragma unroll
        for (int k = 0; k < FOUT; k++) {
            b1 += bz[k] * lzW[j * (2 * FOUT) + k];
            b2 += bh[k] * lhW[j * (2 * FOUT) + k];
        }
        g_p.bz2[j] = b1;
        g_p.bh2[j] = b2;
    } else if (t == FIN * FOUT + FOUT) {
        float m = -1e30f;
        #pragma unroll
        for (int p = 0; p < NP; p++) m = fmaxf(m, att[p]);
        float e[NP], s = 0.f;
        #pragma unroll
        for (int p = 0; p < NP; p++) { e[p] = expf(att[p] - m); s += e[p]; }
        #pragma unroll
        for (int p = 0; p < NP; p++) g_p.probs[p] = e[p] / s;
    }
}

// cnt = 0 ; deg = 1.0 (self loop)
__global__ void k_zero(int n) {
    int i = blockIdx.x * blockDim.x + threadIdx.x;
    if (i < n) { g_cnt[i] = 0; g_deg[i] = 1.0f; }
}

// histogram by dst + weighted degree
__global__ void k_hist(const int* __restrict__ ei, const float* __restrict__ ew, int E) {
    int e = blockIdx.x * blockDim.x + threadIdx.x;
    if (e < E) {
        int d = ei[E + e];
        atomicAdd(&g_cnt[d], 1);
        atomicAdd(&g_deg[d], ew[e]);
    }
}

// single-block exclusive scan of counts -> offsets + cursor; also dinv
__global__ void k_scan(int n, int E) {
    __shared__ int sh[1024];
    int t = threadIdx.x;
    int chunk = (n + 1023) / 1024;
    int lo = t * chunk;
    int hi = min(lo + chunk, n);
    int s = 0;
    for (int i = lo; i < hi; i++) s += g_cnt[i];
    sh[t] = s;
    __syncthreads();
    // Hillis-Steele inclusive scan
    for (int off = 1; off < 1024; off <<= 1) {
        int v = (t >= off) ? sh[t - off] : 0;
        __syncthreads();
        sh[t] += v;
        __syncthreads();
    }
    int run = (t == 0) ? 0 : sh[t - 1];
    for (int i = lo; i < hi; i++) {
        g_offs[i] = run;
        g_cursor[i] = run;
        run += g_cnt[i];
    }
    if (t == 0) g_offs[n] = E;
    // dinv
    for (int i = t; i < n; i += 1024) {
        float d = g_deg[i];
        g_dinv[i] = (d > 0.f) ? rsqrtf(d) : 0.f;
    }
}

// scatter edges into CSR buckets (by dst) with precomputed norm weight
__global__ void k_scatter(const int* __restrict__ ei, const float* __restrict__ ew, int E) {
    int e = blockIdx.x * blockDim.x + threadIdx.x;
    if (e >= E) return;
    int s = ei[e];
    int d = ei[E + e];
    float w = g_dinv[s] * ew[e] * g_dinv[d];
    int pos = atomicAdd(&g_cursor[d], 1);
    g_csr[pos] = make_int2(s, __float_as_int(w));
}

// Main kernel: 4 lanes per node. Lane l owns quads {l, l+4, l+8}.
// Register accumulation (no atomics), coalesced 64B gathers per node,
// fused TGCN-cell epilogue via shared staging.
__global__ void __launch_bounds__(256) k_gather(const float4* __restrict__ xv,
                                                const float* __restrict__ linW,
                                                const float* __restrict__ linb,
                                                float* __restrict__ out, int n) {
    __shared__ float sm[64][F48 + 1];
    int tid = threadIdx.x;
    int l   = tid & 3;           // 0..3
    int ln  = tid >> 2;          // local node 0..63
    int node = blockIdx.x * 64 + ln;

    if (node < n) {
        float di = g_dinv[node];
        float s2 = di * di;
        const float4* xb = xv + (size_t)node * NQ;
        float4 a0 = xb[l],     a1 = xb[l + 4],  a2 = xb[l + 8];
        a0.x *= s2; a0.y *= s2; a0.z *= s2; a0.w *= s2;
        a1.x *= s2; a1.y *= s2; a1.z *= s2; a1.w *= s2;
        a2.x *= s2; a2.y *= s2; a2.z *= s2; a2.w *= s2;

        int rs = g_offs[node];
        int re = g_offs[node + 1];
        int2 nxt;
        if (rs < re) nxt = __ldg(&g_csr[rs]);
        for (int i = rs; i < re; i++) {
            int2 cur = nxt;
            if (i + 1 < re) nxt = __ldg(&g_csr[i + 1]);
            int   s = cur.x;
            float w = __int_as_float(cur.y);
            const float4* xs = xv + (size_t)s * NQ;
            float4 v0 = __ldg(xs + l);
            float4 v1 = __ldg(xs + l + 4);
            float4 v2 = __ldg(xs + l + 8);
            a0.x += w * v0.x; a0.y += w * v0.y; a0.z += w * v0.z; a0.w += w * v0.w;
            a1.x += w * v1.x; a1.y += w * v1.y; a1.z += w * v1.z; a1.w += w * v1.w;
            a2.x += w * v2.x; a2.y += w * v2.y; a2.z += w * v2.z; a2.w += w * v2.w;
        }
        // stage: float index 4*q + r, q = l + 4k
        int b0 = 4 * l, b1 = 4 * (l + 4), b2 = 4 * (l + 8);
        sm[ln][b0 + 0] = a0.x; sm[ln][b0 + 1] = a0.y; sm[ln][b0 + 2] = a0.z; sm[ln][b0 + 3] = a0.w;
        sm[ln][b1 + 0] = a1.x; sm[ln][b1 + 1] = a1.y; sm[ln][b1 + 2] = a1.z; sm[ln][b1 + 3] = a1.w;
        sm[ln][b2 + 0] = a2.x; sm[ln][b2 + 1] = a2.y; sm[ln][b2 + 2] = a2.z; sm[ln][b2 + 3] = a2.w;
    }
    __syncthreads();

    if (node < n && l == 0) {
        const float* a = sm[ln];
        float H[FOUT];
        #pragma unroll
        for (int j = 0; j < FOUT; j++) H[j] = 0.f;

        #pragma unroll
        for (int p = 0; p < NP; p++) {
            float u[FIN];
            #pragma unroll
            for (int f = 0; f < FIN; f++) u[f] = a[f * NP + p];
            float pr = g_p.probs[p];
            #pragma unroll
            for (int j = 0; j < FOUT; j++) {
                float zl = g_p.bz2[j], hl = g_p.bh2[j];
                #pragma unroll
                for (int f = 0; f < FIN; f++) {
                    zl += u[f] * g_p.Mz[f][j];
                    hl += u[f] * g_p.Mh[f][j];
                }
                float z  = 1.f / (1.f + expf(-zl));
                float ht = tanhf(hl);
                H[j] += pr * (1.f - z) * ht;
            }
        }
        #pragma unroll
        for (int j = 0; j < NP; j++) {
            float o = linb[j];
            #pragma unroll
            for (int f = 0; f < FOUT; f++)
                o += fmaxf(H[f], 0.f) * linW[j * FOUT + f];
            out[(size_t)node * NP + j] = o;
        }
    }
}

// ---------------- launch ----------------
extern "C" void kernel_launch(void* const* d_in, const int* in_sizes, int n_in,
                              void* d_out, int out_size) {
    const float* x    = (const float*)d_in[0];
    const int*   ei   = (const int*)  d_in[1];
    const float* ew   = (const float*)d_in[2];
    const float* att  = (const float*)d_in[3];
    const float* Wz   = (const float*)d_in[4];
    const float* bz   = (const float*)d_in[5];
    // d_in[6], d_in[7] = Wr, br : dead (H0 = 0 makes R unused)
    const float* Wh   = (const float*)d_in[8];
    const float* bh   = (const float*)d_in[9];
    const float* lzW  = (const float*)d_in[10];
    const float* lzb  = (const float*)d_in[11];
    // d_in[12], d_in[13] = lrW, lrb : dead
    const float* lhW  = (const float*)d_in[14];
    const float* lhb  = (const float*)d_in[15];
    const float* linW = (const float*)d_in[16];
    const float* linb = (const float*)d_in[17];
    float* out = (float*)d_out;

    int E = in_sizes[2];
    int n = in_sizes[0] / F48;

    const int B = 256;
    k_prep<<<1, 128>>>(att, Wz, bz, Wh, bh, lzW, lzb, lhW, lhb);
    k_zero<<<(n + B - 1) / B, B>>>(n);
    k_hist<<<(E + B - 1) / B, B>>>(ei, ew, E);
    k_scan<<<1, 1024>>>(n, E);
    k_scatter<<<(E + B - 1) / B, B>>>(ei, ew, E);
    k_gather<<<(n + 63) / 64, 256>>>((const float4*)x, linW, linb, out, n);
}

// round 6
// speedup vs baseline: 1.6036x; 1.6036x over previous
#include <cuda_runtime.h>
#include <math.h>

// Problem constants
#define NNODES 50000
#define EMAX   1700000
#define FIN 8
#define FOUT 12
#define NP 6
#define F48 (FIN * NP)      // 48 floats per node
#define NQ  (F48 / 4)       // 12 float4 per node
#define SCAN_B 256

// ---------------- device scratch (no allocations allowed) ----------------
__device__ float g_deg[NNODES];
__device__ float g_dinv[NNODES];
__device__ int   g_cnt[NNODES];
__device__ int   g_offs[NNODES + 1];
__device__ int   g_cursor[NNODES];
__device__ int   g_part[512];          // block partial sums (<= ceil(N/256)=196)
__device__ int2  g_csr[EMAX];          // {src, weight bits}

struct Params {
    float Mz[FIN][FOUT];   // Wz @ lzW[:, :FOUT]^T
    float Mh[FIN][FOUT];   // Wh @ lhW[:, :FOUT]^T
    float bz2[FOUT];
    float bh2[FOUT];
    float probs[NP];
};
__device__ Params g_p;

// ---------------- kernels ----------------

// Fold dense layers into 8x12 matrices; softmax(att). One tiny block.
__global__ void k_prep(const float* __restrict__ att,
                       const float* __restrict__ Wz, const float* __restrict__ bz,
                       const float* __restrict__ Wh, const float* __restrict__ bh,
                       const float* __restrict__ lzW, const float* __restrict__ lzb,
                       const float* __restrict__ lhW, const float* __restrict__ lhb) {
    int t = threadIdx.x;
    if (t < FIN * FOUT) {
        int f = t / FOUT, j = t % FOUT;
        float mz = 0.f, mh = 0.f;
        #pragma unroll
        for (int k = 0; k < FOUT; k++) {
            mz += Wz[f * FOUT + k] * lzW[j * (2 * FOUT) + k];
            mh += Wh[f * FOUT + k] * lhW[j * (2 * FOUT) + k];
        }
        g_p.Mz[f][j] = mz;
        g_p.Mh[f][j] = mh;
    } else if (t < FIN * FOUT + FOUT) {
        int j = t - FIN * FOUT;
        float b1 = lzb[j], b2 = lhb[j];
        #pragma unroll
        for (int k = 0; k < FOUT; k++) {
            b1 += bz[k] * lzW[j * (2 * FOUT) + k];
            b2 += bh[k] * lhW[j * (2 * FOUT) + k];
        }
        g_p.bz2[j] = b1;
        g_p.bh2[j] = b2;
    } else if (t == FIN * FOUT + FOUT) {
        float m = -1e30f;
        #pragma unroll
        for (int p = 0; p < NP; p++) m = fmaxf(m, att[p]);
        float e[NP], s = 0.f;
        #pragma unroll
        for (int p = 0; p < NP; p++) { e[p] = expf(att[p] - m); s += e[p]; }
        #pragma unroll
        for (int p = 0; p < NP; p++) g_p.probs[p] = e[p] / s;
    }
}

// cnt = 0 ; deg = 1.0 (self loop)
__global__ void k_zero(int n) {
    int i = blockIdx.x * blockDim.x + threadIdx.x;
    if (i < n) { g_cnt[i] = 0; g_deg[i] = 1.0f; }
}

// histogram by dst + weighted degree
__global__ void k_hist(const int* __restrict__ ei, const float* __restrict__ ew, int E) {
    int e = blockIdx.x * blockDim.x + threadIdx.x;
    if (e < E) {
        int d = ei[E + e];
        atomicAdd(&g_cnt[d], 1);
        atomicAdd(&g_deg[d], ew[e]);
    }
}

// --- 3-phase parallel scan over g_cnt -> g_offs/g_cursor; also dinv ---

// phase 1: per-block (256-wide) sum of counts
__global__ void k_scan1(int n) {
    __shared__ int sh[SCAN_B];
    int i = blockIdx.x * SCAN_B + threadIdx.x;
    sh[threadIdx.x] = (i < n) ? g_cnt[i] : 0;
    __syncthreads();
    for (int off = SCAN_B / 2; off > 0; off >>= 1) {
        if (threadIdx.x < off) sh[threadIdx.x] += sh[threadIdx.x + off];
        __syncthreads();
    }
    if (threadIdx.x == 0) g_part[blockIdx.x] = sh[0];
}

// phase 2: one block exclusive-scans the partials (nb <= 512)
__global__ void k_scan2(int nb) {
    __shared__ int sh[512];
    int t = threadIdx.x;
    sh[t] = (t < nb) ? g_part[t] : 0;
    __syncthreads();
    for (int off = 1; off < 512; off <<= 1) {
        int v = (t >= off) ? sh[t - off] : 0;
        __syncthreads();
        sh[t] += v;
        __syncthreads();
    }
    if (t < nb) g_part[t] = (t == 0) ? 0 : sh[t - 1];  // exclusive
}

// phase 3: per-block exclusive scan + block prefix -> offs/cursor; dinv
__global__ void k_scan3(int n, int E) {
    __shared__ int sh[SCAN_B];
    int t = threadIdx.x;
    int i = blockIdx.x * SCAN_B + t;
    int v = (i < n) ? g_cnt[i] : 0;
    sh[t] = v;
    __syncthreads();
    for (int off = 1; off < SCAN_B; off <<= 1) {
        int u = (t >= off) ? sh[t - off] : 0;
        __syncthreads();
        sh[t] += u;
        __syncthreads();
    }
    if (i < n) {
        int excl = g_part[blockIdx.x] + sh[t] - v;   // exclusive prefix
        g_offs[i] = excl;
        g_cursor[i] = excl;
        if (i == n - 1) g_offs[n] = E;
        float d = g_deg[i];
        g_dinv[i] = (d > 0.f) ? rsqrtf(d) : 0.f;
    }
}

// scatter edges into CSR buckets (by dst) with precomputed norm weight
__global__ void k_scatter(const int* __restrict__ ei, const float* __restrict__ ew, int E) {
    int e = blockIdx.x * blockDim.x + threadIdx.x;
    if (e >= E) return;
    int s = ei[e];
    int d = ei[E + e];
    float w = g_dinv[s] * ew[e] * g_dinv[d];
    int pos = atomicAdd(&g_cursor[d], 1);
    g_csr[pos] = make_int2(s, __float_as_int(w));
}

// Main kernel: 4 lanes per node. Lane l owns quads {l, l+4, l+8}.
// Register accumulation (no atomics), coalesced 64B gathers per node,
// unroll-by-2 over edges for MLP, fused TGCN-cell epilogue.
__global__ void __launch_bounds__(256) k_gather(const float4* __restrict__ xv,
                                                const float* __restrict__ linW,
                                                const float* __restrict__ linb,
                                                float* __restrict__ out, int n) {
    __shared__ float sm[64][F48 + 1];
    int tid = threadIdx.x;
    int l   = tid & 3;           // 0..3
    int ln  = tid >> 2;          // local node 0..63
    int node = blockIdx.x * 64 + ln;

    if (node < n) {
        float di = g_dinv[node];
        float s2 = di * di;
        const float4* xb = xv + (size_t)node * NQ;
        float4 a0 = xb[l],     a1 = xb[l + 4],  a2 = xb[l + 8];
        a0.x *= s2; a0.y *= s2; a0.z *= s2; a0.w *= s2;
        a1.x *= s2; a1.y *= s2; a1.z *= s2; a1.w *= s2;
        a2.x *= s2; a2.y *= s2; a2.z *= s2; a2.w *= s2;

        int rs = g_offs[node];
        int re = g_offs[node + 1];
        int i = rs;
        // unrolled by 2: 6 independent gathers in flight
        for (; i + 1 < re; i += 2) {
            int2 eA = __ldg(&g_csr[i]);
            int2 eB = __ldg(&g_csr[i + 1]);
            const float4* xA = xv + (size_t)eA.x * NQ;
            const float4* xB = xv + (size_t)eB.x * NQ;
            float wA = __int_as_float(eA.y);
            float wB = __int_as_float(eB.y);
            float4 vA0 = __ldg(xA + l), vA1 = __ldg(xA + l + 4), vA2 = __ldg(xA + l + 8);
            float4 vB0 = __ldg(xB + l), vB1 = __ldg(xB + l + 4), vB2 = __ldg(xB + l + 8);
            a0.x += wA * vA0.x; a0.y += wA * vA0.y; a0.z += wA * vA0.z; a0.w += wA * vA0.w;
            a1.x += wA * vA1.x; a1.y += wA * vA1.y; a1.z += wA * vA1.z; a1.w += wA * vA1.w;
            a2.x += wA * vA2.x; a2.y += wA * vA2.y; a2.z += wA * vA2.z; a2.w += wA * vA2.w;
            a0.x += wB * vB0.x; a0.y += wB * vB0.y; a0.z += wB * vB0.z; a0.w += wB * vB0.w;
            a1.x += wB * vB1.x; a1.y += wB * vB1.y; a1.z += wB * vB1.z; a1.w += wB * vB1.w;
            a2.x += wB * vB2.x; a2.y += wB * vB2.y; a2.z += wB * vB2.z; a2.w += wB * vB2.w;
        }
        if (i < re) {
            int2 e = __ldg(&g_csr[i]);
            const float4* xs = xv + (size_t)e.x * NQ;
            float w = __int_as_float(e.y);
            float4 v0 = __ldg(xs + l), v1 = __ldg(xs + l + 4), v2 = __ldg(xs + l + 8);
            a0.x += w * v0.x; a0.y += w * v0.y; a0.z += w * v0.z; a0.w += w * v0.w;
            a1.x += w * v1.x; a1.y += w * v1.y; a1.z += w * v1.z; a1.w += w * v1.w;
            a2.x += w * v2.x; a2.y += w * v2.y; a2.z += w * v2.z; a2.w += w * v2.w;
        }
        int b0 = 4 * l, b1 = 4 * (l + 4), b2 = 4 * (l + 8);
        sm[ln][b0 + 0] = a0.x; sm[ln][b0 + 1] = a0.y; sm[ln][b0 + 2] = a0.z; sm[ln][b0 + 3] = a0.w;
        sm[ln][b1 + 0] = a1.x; sm[ln][b1 + 1] = a1.y; sm[ln][b1 + 2] = a1.z; sm[ln][b1 + 3] = a1.w;
        sm[ln][b2 + 0] = a2.x; sm[ln][b2 + 1] = a2.y; sm[ln][b2 + 2] = a2.z; sm[ln][b2 + 3] = a2.w;
    }
    __syncthreads();

    if (node < n && l == 0) {
        const float* a = sm[ln];
        float H[FOUT];
        #pragma unroll
        for (int j = 0; j < FOUT; j++) H[j] = 0.f;

        #pragma unroll
        for (int p = 0; p < NP; p++) {
            float u[FIN];
            #pragma unroll
            for (int f = 0; f < FIN; f++) u[f] = a[f * NP + p];
            float pr = g_p.probs[p];
            #pragma unroll
            for (int j = 0; j < FOUT; j++) {
                float zl = g_p.bz2[j], hl = g_p.bh2[j];
                #pragma unroll
                for (int f = 0; f < FIN; f++) {
                    zl += u[f] * g_p.Mz[f][j];
                    hl += u[f] * g_p.Mh[f][j];
                }
                float z  = 1.f / (1.f + expf(-zl));
                float ht = tanhf(hl);
                H[j] += pr * (1.f - z) * ht;
            }
        }
        #pragma unroll
        for (int j = 0; j < NP; j++) {
            float o = linb[j];
            #pragma unroll
            for (int f = 0; f < FOUT; f++)
                o += fmaxf(H[f], 0.f) * linW[j * FOUT + f];
            out[(size_t)node * NP + j] = o;
        }
    }
}

// ---------------- launch ----------------
extern "C" void kernel_launch(void* const* d_in, const int* in_sizes, int n_in,
                              void* d_out, int out_size) {
    const float* x    = (const float*)d_in[0];
    const int*   ei   = (const int*)  d_in[1];
    const float* ew   = (const float*)d_in[2];
    const float* att  = (const float*)d_in[3];
    const float* Wz   = (const float*)d_in[4];
    const float* bz   = (const float*)d_in[5];
    // d_in[6], d_in[7] = Wr, br : dead (H0 = 0 makes R unused)
    const float* Wh   = (const float*)d_in[8];
    const float* bh   = (const float*)d_in[9];
    const float* lzW  = (const float*)d_in[10];
    const float* lzb  = (const float*)d_in[11];
    // d_in[12], d_in[13] = lrW, lrb : dead
    const float* lhW  = (const float*)d_in[14];
    const float* lhb  = (const float*)d_in[15];
    const float* linW = (const float*)d_in[16];
    const float* linb = (const float*)d_in[17];
    float* out = (float*)d_out;

    int E = in_sizes[2];
    int n = in_sizes[0] / F48;

    const int B = 256;
    int nb = (n + SCAN_B - 1) / SCAN_B;   // scan blocks (<=512)

    k_prep<<<1, 128>>>(att, Wz, bz, Wh, bh, lzW, lzb, lhW, lhb);
    k_zero<<<(n + B - 1) / B, B>>>(n);
    k_hist<<<(E + B - 1) / B, B>>>(ei, ew, E);
    k_scan1<<<nb, SCAN_B>>>(n);
    k_scan2<<<1, 512>>>(nb);
    k_scan3<<<nb, SCAN_B>>>(n, E);
    k_scatter<<<(E + B - 1) / B, B>>>(ei, ew, E);
    k_gather<<<(n + 63) / 64, 256>>>((const float4*)x, linW, linb, out, n);
}